// round 6
// baseline (speedup 1.0000x reference)
#include <cuda_runtime.h>
#include <cstdint>
#include <math.h>

#define NSITE 524288          // 32*32*32*16
#define TILE  128
#define NTILES (NSITE / TILE) // 4096
#define NT    512             // 16 warps, one n-tile (8 cols) each
#define GRID  148

#define XS 68                 // X row stride (floats): conflict-free (68 % 32 == 4)
#define HS 132                // H row stride (132 % 32 == 4)

#define SX_OFF 0
#define SH_OFF 8704           // 128*68
#define SP_OFF 25600          // + 128*132
#define SMEM_FLOATS 27648     // + 16*128
#define SMEM_BYTES (SMEM_FLOATS * 4)

__device__ float g_nn[NSITE];
__device__ float g_W1w[16384];              // [W1;W1n]*diag(weight), tf32-rounded
__device__ float g_W2w[32768];              // [W2;W2n], tf32-rounded
__device__ __align__(16) float  g_b1ext[256];   // [b1 ; b1n]
__device__ __align__(16) float2 g_c2 [128];     // (b2[n],  w3[n])
__device__ __align__(16) float2 g_c2n[128];     // (b2n[n], w3n[n])

static __device__ __forceinline__ uint32_t f2tf(float x) {
    uint32_t r; asm("cvt.rna.tf32.f32 %0, %1;" : "=r"(r) : "f"(x)); return r;
}
static __device__ __forceinline__ float tanha(float x) {
    float y; asm("tanh.approx.f32 %0, %1;" : "=f"(y) : "f"(x)); return y;
}
static __device__ __forceinline__ void mma_tf32(
    float& c0, float& c1, float& c2, float& c3,
    uint32_t a0, uint32_t a1, uint32_t a2, uint32_t a3,
    uint32_t b0, uint32_t b1)
{
    asm volatile(
        "mma.sync.aligned.m16n8k8.row.col.f32.tf32.tf32.f32 "
        "{%0,%1,%2,%3}, {%4,%5,%6,%7}, {%8,%9}, {%0,%1,%2,%3};"
        : "+f"(c0), "+f"(c1), "+f"(c2), "+f"(c3)
        : "r"(a0), "r"(a1), "r"(a2), "r"(a3), "r"(b0), "r"(b1));
}

__global__ __launch_bounds__(NT, 1)
void fnn_mma_kernel(
    const float* __restrict__ x_in, const float* __restrict__ ag,
    const float* __restrict__ b3,  const float* __restrict__ b3n,
    const float* __restrict__ max_os_l,
    float* __restrict__ out_os)
{
    extern __shared__ float sm[];
    float* sX = sm + SX_OFF;
    float* sH = sm + SH_OFF;
    float* sP = sm + SP_OFF;

    const int tid = threadIdx.x;
    const int wid = tid >> 5;       // 0..15
    const int lid = tid & 31;
    const int g   = lid >> 2;       // fragment row group
    const int t   = lid & 3;        // fragment k group
    const int n0  = wid * 8;        // this warp's 8 output columns

    const float maxos = expf(max_os_l[0]);
    const float b3v = b3[0], b3nv = b3n[0];

    for (int tile = blockIdx.x; tile < NTILES; tile += GRID) {
        const int base = tile * TILE;

        // ---- stage X tile, tf32-rounded ----
        #pragma unroll
        for (int it = 0; it < 4; it++) {
            int e = tid + it * NT;          // 2048 float4
            int row = e >> 4, col = (e & 15) << 2;
            float4 v = *(const float4*)(x_in + (size_t)(base + row) * 64 + col);
            uint4 u = make_uint4(f2tf(v.x), f2tf(v.y), f2tf(v.z), f2tf(v.w));
            *(uint4*)(sX + row * XS + col) = u;
        }
        __syncthreads();

        #pragma unroll
        for (int mlp = 0; mlp < 2; mlp++) {
            const float*  b1p = g_b1ext + mlp * 128;
            const float2* c2p = mlp ? g_c2n : g_c2;

            // ---- B1 fragments (L1-hot LDG, fixed addresses) ----
            uint32_t B1[16];
            {
                const float* wp = g_W1w + (size_t)(mlp * 128 + n0 + g) * 64;
                #pragma unroll
                for (int ks = 0; ks < 8; ks++) {
                    B1[ks*2+0] = __float_as_uint(__ldg(wp + ks*8 + t));
                    B1[ks*2+1] = __float_as_uint(__ldg(wp + ks*8 + t + 4));
                }
            }

            // ======== GEMM1: H = tanh(X @ W1'^T + b1), K=64 ========
            #pragma unroll
            for (int m = 0; m < 8; m++) {
                const int m0 = m * 16;
                const float* xr0 = sX + (m0 + g) * XS;
                const float* xr1 = xr0 + 8 * XS;
                uint32_t Ar[32];
                #pragma unroll
                for (int ks = 0; ks < 8; ks++) {
                    Ar[ks*4+0] = __float_as_uint(xr0[ks*8 + t]);
                    Ar[ks*4+1] = __float_as_uint(xr1[ks*8 + t]);
                    Ar[ks*4+2] = __float_as_uint(xr0[ks*8 + t + 4]);
                    Ar[ks*4+3] = __float_as_uint(xr1[ks*8 + t + 4]);
                }
                float a0=0.f,a1=0.f,a2=0.f,a3=0.f;   // even-ks chain
                float e0=0.f,e1=0.f,e2=0.f,e3=0.f;   // odd-ks chain
                #pragma unroll
                for (int ks = 0; ks < 8; ks += 2) {
                    mma_tf32(a0,a1,a2,a3, Ar[ks*4],Ar[ks*4+1],Ar[ks*4+2],Ar[ks*4+3],
                             B1[ks*2], B1[ks*2+1]);
                    mma_tf32(e0,e1,e2,e3, Ar[ks*4+4],Ar[ks*4+5],Ar[ks*4+6],Ar[ks*4+7],
                             B1[ks*2+2], B1[ks*2+3]);
                }
                float c0=a0+e0, c1=a1+e1, c2=a2+e2, c3=a3+e3;
                float2 bv = *(const float2*)(b1p + n0 + 2*t);
                uint32_t h0 = f2tf(tanha(c0 + bv.x));
                uint32_t h1 = f2tf(tanha(c1 + bv.y));
                uint32_t h2 = f2tf(tanha(c2 + bv.x));
                uint32_t h3 = f2tf(tanha(c3 + bv.y));
                *(uint2*)(sH + (m0 + g    ) * HS + n0 + 2*t) = make_uint2(h0, h1);
                *(uint2*)(sH + (m0 + g + 8) * HS + n0 + 2*t) = make_uint2(h2, h3);
            }
            __syncthreads();

            // ---- B2 fragments (L1/L2-hot LDG, fixed addresses) ----
            uint32_t B2[32];
            {
                const float* wp = g_W2w + (size_t)mlp * 16384 + (size_t)(n0 + g) * 128;
                #pragma unroll
                for (int ks = 0; ks < 16; ks++) {
                    B2[ks*2+0] = __float_as_uint(__ldg(wp + ks*8 + t));
                    B2[ks*2+1] = __float_as_uint(__ldg(wp + ks*8 + t + 4));
                }
            }

            // ======== GEMM2 + head partials, K=128 ========
            #pragma unroll
            for (int m = 0; m < 8; m++) {
                const int m0 = m * 16;
                const float* hr0 = sH + (m0 + g) * HS;
                const float* hr1 = hr0 + 8 * HS;
                uint32_t Ar[32];
                float a0=0.f,a1=0.f,a2=0.f,a3=0.f;
                float e0=0.f,e1=0.f,e2=0.f,e3=0.f;
                #pragma unroll
                for (int half = 0; half < 2; half++) {
                    const int kb = half * 8;
                    #pragma unroll
                    for (int ks = 0; ks < 8; ks++) {
                        Ar[ks*4+0] = __float_as_uint(hr0[(kb+ks)*8 + t]);
                        Ar[ks*4+1] = __float_as_uint(hr1[(kb+ks)*8 + t]);
                        Ar[ks*4+2] = __float_as_uint(hr0[(kb+ks)*8 + t + 4]);
                        Ar[ks*4+3] = __float_as_uint(hr1[(kb+ks)*8 + t + 4]);
                    }
                    #pragma unroll
                    for (int ks = 0; ks < 8; ks += 2) {
                        mma_tf32(a0,a1,a2,a3, Ar[ks*4],Ar[ks*4+1],Ar[ks*4+2],Ar[ks*4+3],
                                 B2[(kb+ks)*2], B2[(kb+ks)*2+1]);
                        mma_tf32(e0,e1,e2,e3, Ar[ks*4+4],Ar[ks*4+5],Ar[ks*4+6],Ar[ks*4+7],
                                 B2[(kb+ks)*2+2], B2[(kb+ks)*2+3]);
                    }
                }
                float c0=a0+e0, c1=a1+e1, c2=a2+e2, c3=a3+e3;
                float4 cw = *(const float4*)(c2p + n0 + 2*t);   // (b2,w3) x2
                float sum0 = tanha(c0 + cw.x) * cw.y + tanha(c1 + cw.z) * cw.w;
                float sum1 = tanha(c2 + cw.x) * cw.y + tanha(c3 + cw.z) * cw.w;
                sum0 += __shfl_xor_sync(0xffffffffu, sum0, 1);
                sum0 += __shfl_xor_sync(0xffffffffu, sum0, 2);
                sum1 += __shfl_xor_sync(0xffffffffu, sum1, 1);
                sum1 += __shfl_xor_sync(0xffffffffu, sum1, 2);
                if (t == 0) {
                    sP[wid * 128 + m0 + g]     = sum0;
                    sP[wid * 128 + m0 + g + 8] = sum1;
                }
            }
            __syncthreads();

            // ======== head: combine 16 warp partials ========
            if (tid < 128) {
                float s = 0.f;
                #pragma unroll
                for (int w = 0; w < 16; w++) s += sP[w * 128 + tid];
                if (mlp == 0) {
                    float ar = 0.f;
                    #pragma unroll
                    for (int q = 0; q < 16; q++) {
                        float4 xv = *(const float4*)(sX + tid * XS + q * 4);
                        float4 av = __ldg((const float4*)(ag + q * 4));
                        ar += xv.x*av.x + xv.y*av.y + xv.z*av.z + xv.w*av.w;
                    }
                    out_os[base + tid] = tanhf(s + b3v) * maxos + ar;
                } else {
                    g_nn[base + tid] = tanhf(s + b3nv) * maxos;
                }
            }
        }
    }
}

// ---- prep: fold weight into W1, tf32-round all B matrices, pack constants ----
__global__ void fnn_prep_kernel(
    const float* __restrict__ W1,  const float* __restrict__ W1n,
    const float* __restrict__ weight,
    const float* __restrict__ W2,  const float* __restrict__ W2n,
    const float* __restrict__ b1,  const float* __restrict__ b1n,
    const float* __restrict__ b2,  const float* __restrict__ w3,
    const float* __restrict__ b2n, const float* __restrict__ w3n)
{
    int idx = blockIdx.x * blockDim.x + threadIdx.x;   // 32768 threads
    if (idx < 16384) {
        int n = idx >> 6, k = idx & 63;
        float v = (n < 128 ? W1[n * 64 + k] : W1n[(n - 128) * 64 + k]) * weight[k];
        g_W1w[idx] = __uint_as_float(f2tf(v));
    }
    g_W2w[idx] = __uint_as_float(f2tf(idx < 16384 ? W2[idx] : W2n[idx - 16384]));
    if (idx < 128) {
        g_b1ext[idx]       = b1[idx];
        g_b1ext[128 + idx] = b1n[idx];
        g_c2 [idx] = make_float2(b2[idx],  w3[idx]);
        g_c2n[idx] = make_float2(b2n[idx], w3n[idx]);
    }
}

// ---- stencil + sigma ----
__global__ void fnn_stencil_kernel(const float* __restrict__ sigma_l,
                                   float* __restrict__ out)
{
    int idx = blockIdx.x * blockDim.x + threadIdx.x;
    if (idx >= NSITE) return;
    const int ib = idx & 15;
    const int iz = (idx >> 4)  & 31;
    const int iy = (idx >> 9)  & 31;
    const int ix = (idx >> 14) & 31;
    const int xm = (ix + 31) & 31, xp = (ix + 1) & 31;
    const int ym = (iy + 31) & 31, yp = (iy + 1) & 31;
    const int zm = (iz + 31) & 31, zp = (iz + 1) & 31;
#define FNN_I(a, b, c) ((((((a) << 5) + (b)) << 5) + (c)) * 16 + ib)
    float s =
        g_nn[FNN_I(xm, iy, zm)] + g_nn[FNN_I(xm, iy, zp)] +
        g_nn[FNN_I(xp, iy, zm)] + g_nn[FNN_I(xp, iy, zp)] +
        g_nn[FNN_I(ix, ym, zm)] + g_nn[FNN_I(ix, ym, zp)] +
        g_nn[FNN_I(ix, yp, zm)] + g_nn[FNN_I(ix, yp, zp)];
#undef FNN_I
    out[idx] += 0.125f * s;
    out[NSITE + idx] = expf(sigma_l[0]);
}

extern "C" void kernel_launch(void* const* d_in, const int* in_sizes, int n_in,
                              void* d_out, int out_size)
{
    const float* x_in     = (const float*)d_in[0];
    const float* weight   = (const float*)d_in[1];
    const float* ag       = (const float*)d_in[2];
    const float* W1       = (const float*)d_in[3];
    const float* b1       = (const float*)d_in[4];
    const float* W2       = (const float*)d_in[5];
    const float* b2       = (const float*)d_in[6];
    const float* W3       = (const float*)d_in[7];
    const float* b3       = (const float*)d_in[8];
    const float* W1n      = (const float*)d_in[9];
    const float* b1n      = (const float*)d_in[10];
    const float* W2n      = (const float*)d_in[11];
    const float* b2n      = (const float*)d_in[12];
    const float* W3n      = (const float*)d_in[13];
    const float* b3n      = (const float*)d_in[14];
    const float* max_os_l = (const float*)d_in[15];
    const float* sigma_l  = (const float*)d_in[16];
    float* out = (float*)d_out;

    fnn_prep_kernel<<<128, 256>>>(W1, W1n, weight, W2, W2n,
                                  b1, b1n, b2, W3, b2n, W3n);

    cudaFuncSetAttribute(fnn_mma_kernel,
                         cudaFuncAttributeMaxDynamicSharedMemorySize, SMEM_BYTES);
    fnn_mma_kernel<<<GRID, NT, SMEM_BYTES>>>(
        x_in, ag, b3, b3n, max_os_l, out);

    fnn_stencil_kernel<<<NSITE / 256, 256>>>(sigma_l, out);
}

// round 9
// speedup vs baseline: 1.2845x; 1.2845x over previous
#include <cuda_runtime.h>
#include <cstdint>
#include <math.h>

#define NSITE 524288          // 32*32*32*16
#define TILE  128
#define NTILES (NSITE / TILE) // 4096
#define NT    512             // 16 warps, one 8-col n-tile each
#define GRID  148

// SMEM float offsets (fragment-resident layouts)
#define XF_OFF  0             // X frags:  [m][ks][lane][r]  8*8*32*4   = 8192
#define HF_OFF  8192          // H frags:  [mlp][m][ks2][lane][r] 2*8*16*32*4 = 32768
#define SP0_OFF 40960         // head partials mlp0: 16*128 = 2048
#define SP1_OFF 43008         // head partials mlp1: 2048
#define SAR_OFF 45056         // AR dots: 128
#define SMEM_FLOATS 45184
#define SMEM_BYTES (SMEM_FLOATS * 4)

__device__ float g_nn[NSITE];
__device__ float g_W1w[16384];              // [W1;W1n]*diag(weight), tf32
__device__ float g_W2w[32768];              // [W2;W2n], tf32
__device__ __align__(16) float  g_b1ext[256];
__device__ __align__(16) float2 g_c2 [128];   // (b2, w3)
__device__ __align__(16) float2 g_c2n[128];   // (b2n, w3n)

static __device__ __forceinline__ uint32_t f2tf(float x) {
    uint32_t r; asm("cvt.rna.tf32.f32 %0, %1;" : "=r"(r) : "f"(x)); return r;
}
static __device__ __forceinline__ float tanha(float x) {
    float y; asm("tanh.approx.f32 %0, %1;" : "=f"(y) : "f"(x)); return y;
}
static __device__ __forceinline__ void mma_tf32(
    float& c0, float& c1, float& c2, float& c3,
    uint32_t a0, uint32_t a1, uint32_t a2, uint32_t a3,
    uint32_t b0, uint32_t b1)
{
    asm volatile(
        "mma.sync.aligned.m16n8k8.row.col.f32.tf32.tf32.f32 "
        "{%0,%1,%2,%3}, {%4,%5,%6,%7}, {%8,%9}, {%0,%1,%2,%3};"
        : "+f"(c0), "+f"(c1), "+f"(c2), "+f"(c3)
        : "r"(a0), "r"(a1), "r"(a2), "r"(a3), "r"(b0), "r"(b1));
}

__global__ __launch_bounds__(NT, 1)
void fnn_mma_kernel(
    const float* __restrict__ x_in, const float* __restrict__ ag,
    const float* __restrict__ b3,  const float* __restrict__ b3n,
    const float* __restrict__ max_os_l,
    float* __restrict__ out_os)
{
    extern __shared__ float sm[];
    const int tid = threadIdx.x;
    const int wid = tid >> 5;       // 0..15 -> n-tile / GEMM2 k-block
    const int lid = tid & 31;
    const int g   = lid >> 2;
    const int t   = lid & 3;
    const int n0  = wid * 8;

    const float maxos = expf(max_os_l[0]);
    const float b3v = b3[0], b3nv = b3n[0];

    // ---- persistent B fragments (one-time LDG) ----
    uint32_t B1[2][16], B2[2][32];
    #pragma unroll
    for (int mlp = 0; mlp < 2; mlp++) {
        const float* wp = g_W1w + (size_t)(mlp * 128 + n0 + g) * 64;
        #pragma unroll
        for (int ks = 0; ks < 8; ks++) {
            B1[mlp][ks*2+0] = __float_as_uint(__ldg(wp + ks*8 + t));
            B1[mlp][ks*2+1] = __float_as_uint(__ldg(wp + ks*8 + t + 4));
        }
        const float* wp2 = g_W2w + (size_t)mlp * 16384 + (size_t)(n0 + g) * 128;
        #pragma unroll
        for (int ks = 0; ks < 16; ks++) {
            B2[mlp][ks*2+0] = __float_as_uint(__ldg(wp2 + ks*8 + t));
            B2[mlp][ks*2+1] = __float_as_uint(__ldg(wp2 + ks*8 + t + 4));
        }
    }
    // per-warp bias / head constants
    const float2 bv0 = *(const float2*)(g_b1ext + n0 + 2*t);
    const float2 bv1 = *(const float2*)(g_b1ext + 128 + n0 + 2*t);
    const float4 cw0 = *(const float4*)(&g_c2 [n0 + 2*t]);
    const float4 cw1 = *(const float4*)(&g_c2n[n0 + 2*t]);
    // staging constants: this thread always handles cols cst..cst+3
    const int cst = (tid & 15) * 4;
    const float4 ag4 = *(const float4*)(ag + cst);

    for (int tile = blockIdx.x; tile < NTILES; tile += GRID) {
        const int base = tile * TILE;

        // ---- stage X into fragment layout + AR dot ----
        #pragma unroll
        for (int it = 0; it < 4; it++) {
            int row = (tid >> 4) + it * 32;          // 0..127
            float4 v = *(const float4*)(x_in + (size_t)(base + row) * 64 + cst);
            float pr = v.x*ag4.x + v.y*ag4.y + v.z*ag4.z + v.w*ag4.w;
            pr += __shfl_xor_sync(0xffffffffu, pr, 8);
            pr += __shfl_xor_sync(0xffffffffu, pr, 4);
            pr += __shfl_xor_sync(0xffffffffu, pr, 2);
            pr += __shfl_xor_sync(0xffffffffu, pr, 1);
            if ((tid & 15) == 0) sm[SAR_OFF + row] = pr;
            int m  = row >> 4, gg = row & 7, hi = (row >> 3) & 1;
            int ks = cst >> 3;
            int r  = hi + ((cst & 4) >> 1);          // hi + 2*hi4
            float* p = sm + XF_OFF + m*1024 + ks*128 + gg*16 + r;
            p[0]  = __uint_as_float(f2tf(v.x));
            p[4]  = __uint_as_float(f2tf(v.y));
            p[8]  = __uint_as_float(f2tf(v.z));
            p[12] = __uint_as_float(f2tf(v.w));
        }
        __syncthreads();   // S1

        // ---- fused GEMM1 (both MLPs): H = tanh(X W1'^T + b1) in frag layout ----
        #pragma unroll
        for (int m = 0; m < 8; m++) {
            const float* ap = sm + XF_OFF + m*1024 + lid*4;
            uint4 A[8];
            #pragma unroll
            for (int ks = 0; ks < 8; ks++) A[ks] = *(const uint4*)(ap + ks*128);
            float oa0=0,oa1=0,oa2=0,oa3=0, ob0=0,ob1=0,ob2=0,ob3=0;
            float na0=0,na1=0,na2=0,na3=0, nb0=0,nb1=0,nb2=0,nb3=0;
            #pragma unroll
            for (int ks = 0; ks < 8; ks += 2) {
                mma_tf32(oa0,oa1,oa2,oa3, A[ks].x,A[ks].y,A[ks].z,A[ks].w,
                         B1[0][ks*2], B1[0][ks*2+1]);
                mma_tf32(na0,na1,na2,na3, A[ks].x,A[ks].y,A[ks].z,A[ks].w,
                         B1[1][ks*2], B1[1][ks*2+1]);
                mma_tf32(ob0,ob1,ob2,ob3, A[ks+1].x,A[ks+1].y,A[ks+1].z,A[ks+1].w,
                         B1[0][ks*2+2], B1[0][ks*2+3]);
                mma_tf32(nb0,nb1,nb2,nb3, A[ks+1].x,A[ks+1].y,A[ks+1].z,A[ks+1].w,
                         B1[1][ks*2+2], B1[1][ks*2+3]);
            }
            // H-frag write offsets (producer n-tile wid == consumer k-block wid)
            // consecutive floats = rows {g, g+8} of the SAME column:
            //   l0 -> col 2t   : pair (h0, h2)
            //   l1 -> col 2t+1 : pair (h1, h3)
            const int l0 = 16*g + 4*((2*t)   & 3) + 2*(((2*t)   >> 2));
            const int l1 = 16*g + 4*((2*t+1) & 3) + 2*(((2*t+1) >> 2));
            {   // os
                float h0 = __uint_as_float(f2tf(tanha(oa0+ob0 + bv0.x)));
                float h1 = __uint_as_float(f2tf(tanha(oa1+ob1 + bv0.y)));
                float h2 = __uint_as_float(f2tf(tanha(oa2+ob2 + bv0.x)));
                float h3 = __uint_as_float(f2tf(tanha(oa3+ob3 + bv0.y)));
                float* hp = sm + HF_OFF + m*2048 + wid*128;
                *(float2*)(hp + l0) = make_float2(h0, h2);
                *(float2*)(hp + l1) = make_float2(h1, h3);
            }
            {   // nn
                float h0 = __uint_as_float(f2tf(tanha(na0+nb0 + bv1.x)));
                float h1 = __uint_as_float(f2tf(tanha(na1+nb1 + bv1.y)));
                float h2 = __uint_as_float(f2tf(tanha(na2+nb2 + bv1.x)));
                float h3 = __uint_as_float(f2tf(tanha(na3+nb3 + bv1.y)));
                float* hp = sm + HF_OFF + 16384 + m*2048 + wid*128;
                *(float2*)(hp + l0) = make_float2(h0, h2);
                *(float2*)(hp + l1) = make_float2(h1, h3);
            }
        }
        __syncthreads();   // S2

        // ---- GEMM2 + heads ----
        #pragma unroll
        for (int mlp = 0; mlp < 2; mlp++) {
            const float4 cw = mlp ? cw1 : cw0;
            float* sP = sm + (mlp ? SP1_OFF : SP0_OFF);
            #pragma unroll
            for (int m = 0; m < 8; m++) {
                const float* ap = sm + HF_OFF + mlp*16384 + m*2048 + lid*4;
                float a0=0,a1=0,a2=0,a3=0, e0=0,e1=0,e2=0,e3=0;
                #pragma unroll
                for (int half = 0; half < 2; half++) {
                    uint4 A[8];
                    #pragma unroll
                    for (int ks = 0; ks < 8; ks++)
                        A[ks] = *(const uint4*)(ap + (half*8 + ks)*128);
                    #pragma unroll
                    for (int ks = 0; ks < 8; ks += 2) {
                        const int kk = half*8 + ks;
                        mma_tf32(a0,a1,a2,a3, A[ks].x,A[ks].y,A[ks].z,A[ks].w,
                                 B2[mlp][kk*2], B2[mlp][kk*2+1]);
                        mma_tf32(e0,e1,e2,e3, A[ks+1].x,A[ks+1].y,A[ks+1].z,A[ks+1].w,
                                 B2[mlp][kk*2+2], B2[mlp][kk*2+3]);
                    }
                }
                float c0=a0+e0, c1=a1+e1, c2=a2+e2, c3=a3+e3;
                float sum0 = tanha(c0 + cw.x)*cw.y + tanha(c1 + cw.z)*cw.w;
                float sum1 = tanha(c2 + cw.x)*cw.y + tanha(c3 + cw.z)*cw.w;
                sum0 += __shfl_xor_sync(0xffffffffu, sum0, 1);
                sum0 += __shfl_xor_sync(0xffffffffu, sum0, 2);
                sum1 += __shfl_xor_sync(0xffffffffu, sum1, 1);
                sum1 += __shfl_xor_sync(0xffffffffu, sum1, 2);
                if (t == 0) {
                    sP[wid*128 + m*16 + g]     = sum0;
                    sP[wid*128 + m*16 + g + 8] = sum1;
                }
            }
            __syncthreads();   // S3 (mlp0) / S4 (mlp1)

            if (mlp == 0) {
                if (tid < 128) {
                    float s = 0.f;
                    #pragma unroll
                    for (int w = 0; w < 16; w++) s += sm[SP0_OFF + w*128 + tid];
                    out_os[base + tid] = tanhf(s + b3v) * maxos + sm[SAR_OFF + tid];
                }
            } else {
                if (tid < 128) {
                    float s = 0.f;
                    #pragma unroll
                    for (int w = 0; w < 16; w++) s += sm[SP1_OFF + w*128 + tid];
                    g_nn[base + tid] = tanhf(s + b3nv) * maxos;
                }
            }
        }
        __syncthreads();   // protect SAR/XF/HF/SP before next tile
    }
}

// ---- prep: fold weight into W1, tf32-round B matrices, pack constants ----
__global__ void fnn_prep_kernel(
    const float* __restrict__ W1,  const float* __restrict__ W1n,
    const float* __restrict__ weight,
    const float* __restrict__ W2,  const float* __restrict__ W2n,
    const float* __restrict__ b1,  const float* __restrict__ b1n,
    const float* __restrict__ b2,  const float* __restrict__ w3,
    const float* __restrict__ b2n, const float* __restrict__ w3n)
{
    int idx = blockIdx.x * blockDim.x + threadIdx.x;   // 32768 threads
    if (idx < 16384) {
        int n = idx >> 6, k = idx & 63;
        float v = (n < 128 ? W1[n * 64 + k] : W1n[(n - 128) * 64 + k]) * weight[k];
        g_W1w[idx] = __uint_as_float(f2tf(v));
    }
    g_W2w[idx] = __uint_as_float(f2tf(idx < 16384 ? W2[idx] : W2n[idx - 16384]));
    if (idx < 128) {
        g_b1ext[idx]       = b1[idx];
        g_b1ext[128 + idx] = b1n[idx];
        g_c2 [idx] = make_float2(b2[idx],  w3[idx]);
        g_c2n[idx] = make_float2(b2n[idx], w3n[idx]);
    }
}

// ---- stencil + sigma ----
__global__ void fnn_stencil_kernel(const float* __restrict__ sigma_l,
                                   float* __restrict__ out)
{
    int idx = blockIdx.x * blockDim.x + threadIdx.x;
    if (idx >= NSITE) return;
    const int ib = idx & 15;
    const int iz = (idx >> 4)  & 31;
    const int iy = (idx >> 9)  & 31;
    const int ix = (idx >> 14) & 31;
    const int xm = (ix + 31) & 31, xp = (ix + 1) & 31;
    const int ym = (iy + 31) & 31, yp = (iy + 1) & 31;
    const int zm = (iz + 31) & 31, zp = (iz + 1) & 31;
#define FNN_I(a, b, c) ((((((a) << 5) + (b)) << 5) + (c)) * 16 + ib)
    float s =
        g_nn[FNN_I(xm, iy, zm)] + g_nn[FNN_I(xm, iy, zp)] +
        g_nn[FNN_I(xp, iy, zm)] + g_nn[FNN_I(xp, iy, zp)] +
        g_nn[FNN_I(ix, ym, zm)] + g_nn[FNN_I(ix, ym, zp)] +
        g_nn[FNN_I(ix, yp, zm)] + g_nn[FNN_I(ix, yp, zp)];
#undef FNN_I
    out[idx] += 0.125f * s;
    out[NSITE + idx] = expf(sigma_l[0]);
}

extern "C" void kernel_launch(void* const* d_in, const int* in_sizes, int n_in,
                              void* d_out, int out_size)
{
    const float* x_in     = (const float*)d_in[0];
    const float* weight   = (const float*)d_in[1];
    const float* ag       = (const float*)d_in[2];
    const float* W1       = (const float*)d_in[3];
    const float* b1       = (const float*)d_in[4];
    const float* W2       = (const float*)d_in[5];
    const float* b2       = (const float*)d_in[6];
    const float* W3       = (const float*)d_in[7];
    const float* b3       = (const float*)d_in[8];
    const float* W1n      = (const float*)d_in[9];
    const float* b1n      = (const float*)d_in[10];
    const float* W2n      = (const float*)d_in[11];
    const float* b2n      = (const float*)d_in[12];
    const float* W3n      = (const float*)d_in[13];
    const float* b3n      = (const float*)d_in[14];
    const float* max_os_l = (const float*)d_in[15];
    const float* sigma_l  = (const float*)d_in[16];
    float* out = (float*)d_out;

    fnn_prep_kernel<<<128, 256>>>(W1, W1n, weight, W2, W2n,
                                  b1, b1n, b2, W3, b2n, W3n);

    cudaFuncSetAttribute(fnn_mma_kernel,
                         cudaFuncAttributeMaxDynamicSharedMemorySize, SMEM_BYTES);
    fnn_mma_kernel<<<GRID, NT, SMEM_BYTES>>>(
        x_in, ag, b3, b3n, max_os_l, out);

    fnn_stencil_kernel<<<NSITE / 256, 256>>>(sigma_l, out);
}